// round 13
// baseline (speedup 1.0000x reference)
#include <cuda_runtime.h>
#include <cuda_bf16.h>
#include <cstdint>

// Problem shape (fixed for this registry entry)
#define B     8
#define T     200
#define U1    101        // U+1
#define V     1024
#define UD    104        // padded cells per diagonal row
#define ND    300        // single-step diagonals (T + U1 - 1)
#define NPR   168        // padded pair-rows per batch (21 blocks of 8)
#define NPREAL 150       // real pair rows (ceil(ND/2))
#define CHROWS 42        // pair rows per staging chunk
#define NCH   4          // staging chunks (4*42 = 168)
#define LN2   0.6931471805599453f
#define LOG2E 1.4426950408889634f

// Pair-step coefficient planes (SoA for conflict-free LDS):
//   A-plane: uint32 = bf16x2 (c0, c1) per cell
//   B-plane: bf16   = c2 per cell
// a_{d+2}(u) = c0*a(u) + c1*a(u-1) + c2*a(u-2)
__device__ __align__(16) uint32_t      g_pA[B * NPR * UD];
__device__ __align__(16) __nv_bfloat16 g_pB[B * NPR * UD];

__device__ __forceinline__ uint32_t smem_u32(const void* p) {
    uint32_t a;
    asm("{ .reg .u64 t; cvta.to.shared.u64 t, %1; cvt.u32.u64 %0, t; }"
        : "=r"(a) : "l"(p));
    return a;
}

// ---------------------------------------------------------------------------
// FMA-pipe exp: exp(x) = 2^(x*log2e), |x| small (logits ~ N(0,1)).
// Magic-constant rounding + degree-4 poly; no MUFU, no CVT.
// rel err <= ~5e-5, far below the bf16 (4e-3) the result is stored in.
// ---------------------------------------------------------------------------
__device__ __forceinline__ float fexp(float x) {
    const float MAGIC = 12582912.0f;               // 1.5 * 2^23
    float z = fmaf(x, LOG2E, MAGIC);
    int   k = __float_as_int(z) - 0x4B400000;      // round(x*log2e)
    float r = z - MAGIC;
    float f = fmaf(x, LOG2E, -r);                  // exact residual, [-0.5,0.5]
    float p = fmaf(f, 0.0096181291f, 0.0555041087f);
    p = fmaf(f, p, 0.2402265069f);
    p = fmaf(f, p, 0.6931471806f);
    p = fmaf(f, p, 1.0f);                          // 2^f
    return __int_as_float(__float_as_int(p) + (k << 23));
}

// Single-step scores (neutral-padded, proven R5..R11):
//   Bl(r,u) = exp(blank[t-1,u]) (1 if invalid/t<1)
//   Lc(r,u) = exp(lab[t,u])     (0 if invalid/u<1),  t = r-u
__device__ __forceinline__ float2 get_BL(const float* __restrict__ logits,
                                         const int* __restrict__ labels,
                                         int b, int r, int u) {
    if (r < 0 || u >= U1) return make_float2(1.0f, 0.0f);
    int t = r - u;
    if (t < 0 || t >= T) return make_float2(1.0f, 0.0f);
    float Bl = 1.0f, Lc = 0.0f;
    if (t >= 1)
        Bl = fexp(logits[((long)(b * T + (t - 1)) * U1 + u) * V]);
    if (u >= 1)
        Lc = fexp(logits[((long)(b * T + t) * U1 + (u - 1)) * V
                         + labels[b * (U1 - 1) + (u - 1)]]);
    return make_float2(Bl, Lc);
}

// ---------------------------------------------------------------------------
// Kernel 1: gather + compose into pair coefficients. One 128-thread block per
// (batch, pair-row); thread u computes s1=(Bl,Lc)(r1,u) and s2=(r1+1,u) with
// the FMA-pipe exp (4 exps/thread), shares s1 through smem so the (u-1)
// evaluation is NOT recomputed (was 2 extra exps). Pad rows write dead maps
// (zeros) — they only run after the dp snapshot. Also zero-inits out.
// ---------------------------------------------------------------------------
__global__ void __launch_bounds__(128, 8)
gather_kernel(const float* __restrict__ logits,
              const int* __restrict__ labels,
              const int* __restrict__ loglen,
              const int* __restrict__ lablen,
              float* __restrict__ out) {
    __shared__ float2 s1row[UD];

    const int bp = blockIdx.x;                     // b * NPR + p
    const int b  = bp / NPR;
    const int p  = bp % NPR;
    const int u  = threadIdx.x;
    if (bp == 0 && u == 0) out[0] = 0.0f;

    const bool live = (p < NPREAL);
    float2 s1 = make_float2(1.0f, 0.0f), s2 = make_float2(1.0f, 0.0f);
    if (live && u < UD) {
        int off = (loglen[b] + lablen[b]) & 1;     // odd lengths: identity pre-row
        int r1  = 2 * p - off;
        s1 = get_BL(logits, labels, b, r1,     u);
        s2 = get_BL(logits, labels, b, r1 + 1, u);
        s1row[u] = s1;
    }
    __syncthreads();
    if (u >= UD) return;

    float c0 = 0.0f, c1 = 0.0f, c2 = 0.0f;         // pad rows: dead map
    if (live) {
        float2 s1m = (u >= 1) ? s1row[u - 1] : make_float2(1.0f, 0.0f);
        c0 = s2.x * s1.x;                          // B2*B1
        c1 = fmaf(s2.x, s1.y, s2.y * s1m.x);       // B2*L1 + L2*B1(u-1)
        c2 = s2.y * s1m.y;                         // L2*L1(u-1)
    }
    int idx = (b * NPR + p) * UD + u;
    __nv_bfloat162 p01 = __floats2bfloat162_rn(c0, c1);
    g_pA[idx] = *reinterpret_cast<uint32_t*>(&p01);
    g_pB[idx] = __float2bfloat16_rn(c2);
}

// ---------------------------------------------------------------------------
// Kernel 2 (unchanged from R11 — proven 8.5us): one 32-thread CTA per batch.
// Chunked bulk-copy staging (4 chunks). Pair-step wavefront: every step reads
// only OLD state -> no intra-step serial chain; both shfls issue at step top.
// lane L owns u = 4L..4L+3. Exact power-of-2 renorm every 8 pair-steps.
// Final block snapshots state at pair capRem.
// ---------------------------------------------------------------------------
struct DPState { float a0, a1, a2, a3; };
struct PairBuf { uint4 ab[8]; uint2 c2[8]; };

__device__ __forceinline__ float bflo(uint32_t x) {
    return __int_as_float((int)(x << 16));
}
__device__ __forceinline__ float bfhi(uint32_t x) {
    return __int_as_float((int)(x & 0xFFFF0000u));
}

__device__ __forceinline__ void pair_step(DPState& s, uint4 ab, uint2 cc,
                                          int lsrc) {
    float p3 = __shfl_sync(0xffffffffu, s.a3, lsrc);   // a(u-1) for cell 0
    float p2 = __shfl_sync(0xffffffffu, s.a2, lsrc);   // a(u-2) for cell 0
    float n0 = fmaf(bflo(ab.x), s.a0,
               fmaf(bfhi(ab.x), p3,   bflo(cc.x) * p2));
    float n1 = fmaf(bflo(ab.y), s.a1,
               fmaf(bfhi(ab.y), s.a0, bfhi(cc.x) * p3));
    float n2 = fmaf(bflo(ab.z), s.a2,
               fmaf(bfhi(ab.z), s.a1, bflo(cc.y) * s.a0));
    float n3 = fmaf(bflo(ab.w), s.a3,
               fmaf(bfhi(ab.w), s.a2, bfhi(cc.y) * s.a1));
    s.a0 = n0; s.a1 = n1; s.a2 = n2; s.a3 = n3;
}

__device__ __forceinline__ void renorm(DPState& s, int& S) {
    float mx = fmaxf(fmaxf(s.a0, s.a1), fmaxf(s.a2, s.a3));
    unsigned mxi = __reduce_max_sync(0xffffffffu, (unsigned)__float_as_int(mx));
    int e = (int)(mxi >> 23) - 127;
    float sc = __int_as_float((127 - e) << 23);        // 2^-e, exact
    s.a0 *= sc; s.a1 *= sc; s.a2 *= sc; s.a3 *= sc;
    S += e;
}

__global__ void __launch_bounds__(32, 1)
dp_kernel(const int* __restrict__ loglen,
          const int* __restrict__ lablen,
          float* __restrict__ out) {
    extern __shared__ __align__(16) char sm[];
    uint32_t* smA = reinterpret_cast<uint32_t*>(sm);
    __nv_bfloat16* smB = reinterpret_cast<__nv_bfloat16*>(sm + NPR * UD * 4);
    __shared__ __align__(8) unsigned long long mbars[NCH];

    const int b    = blockIdx.x;
    const int lane = threadIdx.x;
    const int lsrc = (lane + 31) & 31;

    if (lane == 0) {
        #pragma unroll
        for (int c = 0; c < NCH; ++c)
            asm volatile("mbarrier.init.shared.b64 [%0], %1;"
                         :: "r"(smem_u32(&mbars[c])), "r"(1) : "memory");
        asm volatile("fence.proxy.async.shared::cta;" ::: "memory");
        #pragma unroll 1
        for (int c = 0; c < NCH; ++c) {
            uint32_t txA = CHROWS * UD * 4u;
            uint32_t txB = CHROWS * UD * 2u;
            uint32_t mb  = smem_u32(&mbars[c]);
            asm volatile("mbarrier.arrive.expect_tx.shared.b64 _, [%0], %1;"
                         :: "r"(mb), "r"(txA + txB) : "memory");
            asm volatile(
                "cp.async.bulk.shared::cluster.global.mbarrier::complete_tx::bytes"
                " [%0], [%1], %2, [%3];"
                :: "r"(smem_u32(smA + c * CHROWS * UD)),
                   "l"(g_pA + (size_t)(b * NPR + c * CHROWS) * UD),
                   "r"(txA), "r"(mb) : "memory");
            asm volatile(
                "cp.async.bulk.shared::cluster.global.mbarrier::complete_tx::bytes"
                " [%0], [%1], %2, [%3];"
                :: "r"(smem_u32(smB + c * CHROWS * UD)),
                   "l"(g_pB + (size_t)(b * NPR + c * CHROWS) * UD),
                   "r"(txB), "r"(mb) : "memory");
        }
    }
    __syncwarp();

    int cw = 0;
    auto ensure = [&](int c) {
        while (cw <= c) {
            uint32_t mb = smem_u32(&mbars[cw]);
            uint32_t done = 0;
            while (!done)
                asm volatile(
                    "{\n\t.reg .pred p;\n\t"
                    "mbarrier.try_wait.parity.acquire.cta.shared::cta.b64 p, [%1], %2;\n\t"
                    "selp.b32 %0, 1, 0, p;\n\t}"
                    : "=r"(done) : "r"(mb), "r"(0u) : "memory");
            ++cw;
        }
    };

    const int Tb     = loglen[b];
    const int Lb     = lablen[b];
    const int nSteps = Tb + Lb;
    const int nPair  = (nSteps + 1) >> 1;
    const int blkTot = (nPair + 7) >> 3;
    const int nFull  = blkTot - 1;
    const int capRem = (nPair - 1) - nFull * 8;

    DPState s;
    s.a0 = (lane == 0) ? 1.0f : 0.0f;
    s.a1 = 0.0f; s.a2 = 0.0f; s.a3 = 0.0f;
    int S = 0;
    float c0 = 0.0f, c1 = 0.0f, c2 = 0.0f, c3 = 0.0f;

    const uint4* pa = reinterpret_cast<const uint4*>(smA) + lane;
    const uint2* pb = reinterpret_cast<const uint2*>(smB) + lane;

    PairBuf bufA, bufB;
    auto pref = [&](PairBuf& buf, int blk) {
        int base = blk * 8 * 26;
        #pragma unroll
        for (int k = 0; k < 8; ++k) {
            buf.ab[k] = pa[base + k * 26];
            buf.c2[k] = pb[base + k * 26];
        }
    };
    auto comp = [&](PairBuf& buf) {
        renorm(s, S);
        #pragma unroll
        for (int k = 0; k < 8; ++k)
            pair_step(s, buf.ab[k], buf.c2[k], lsrc);
    };
    auto compLast = [&](PairBuf& buf) {
        renorm(s, S);
        #pragma unroll
        for (int k = 0; k < 8; ++k) {
            pair_step(s, buf.ab[k], buf.c2[k], lsrc);
            if (k == capRem) { c0 = s.a0; c1 = s.a1; c2 = s.a2; c3 = s.a3; }
        }
    };
    auto cb = [](int blk) { return (8 * blk + 7) / CHROWS; };

    ensure(cb(0));
    pref(bufA, 0);
    int blk = 0;
    #pragma unroll 1
    while (blk + 2 <= nFull) {
        ensure(cb(blk + 1)); pref(bufB, blk + 1); comp(bufA);
        ensure(cb(blk + 2)); pref(bufA, blk + 2); comp(bufB);
        blk += 2;
    }
    if (blk == nFull) {
        compLast(bufA);
    } else {
        ensure(cb(blk + 1)); pref(bufB, blk + 1); comp(bufA);
        compLast(bufB);
    }

    if (lane == (Lb >> 2)) {
        int ck = Lb & 3;
        float cap = (ck == 0) ? c0 : (ck == 1) ? c1 : (ck == 2) ? c2 : c3;
        float loss = -(log2f(cap) + (float)S) * LN2;
        atomicAdd(out, loss * (1.0f / B));
    }
}

// ---------------------------------------------------------------------------
extern "C" void kernel_launch(void* const* d_in, const int* in_sizes, int n_in,
                              void* d_out, int out_size) {
    const float* logits = (const float*)d_in[0];
    const int*   labels = (const int*)d_in[1];
    const int*   loglen = (const int*)d_in[2];
    const int*   lablen = (const int*)d_in[3];
    float* out = (float*)d_out;

    const int smem_bytes = NPR * UD * 4 + NPR * UD * 2;  // 104832 B

    cudaFuncSetAttribute(dp_kernel,
                         cudaFuncAttributeMaxDynamicSharedMemorySize,
                         smem_bytes);

    gather_kernel<<<B * NPR, 128>>>(logits, labels, loglen, lablen, out);
    dp_kernel<<<B, 32, smem_bytes>>>(loglen, lablen, out);
}